// round 16
// baseline (speedup 1.0000x reference)
#include <cuda_runtime.h>
#include <cuda_fp16.h>
#include <math.h>
#include <stdint.h>

// Problem constants
#define D_MODEL 1024
#define N_HEADS 16
#define N_GROUPS 4
#define HEAD_DIM 64
#define KV_HEADS 4
#define D_KV 256
#define BATCH 2
#define SEQ 2048
#define BS (BATCH * SEQ)   // 4096

// Scratch buffers (device globals)
__device__ __half g_Xh[BS * D_MODEL];        // fp16 x
__device__ __half g_WqT[D_MODEL * D_MODEL];  // [N][K] fp16
__device__ __half g_WkT[D_KV * D_MODEL];
__device__ __half g_WvT[D_KV * D_MODEL];
__device__ __half g_WoT[D_MODEL * D_MODEL];
__device__ __half g_Qh[BS * D_MODEL];
__device__ __half g_Kh[BS * D_KV];
__device__ __half g_Vh[BS * D_KV];
__device__ __half g_Oh[BS * D_MODEL];
// fragment-packed K/V tiles: [b*4+kh][kt][4096 halves]
__device__ __half g_Kp[BATCH * KV_HEADS * (SEQ / 64) * 4096];
__device__ __half g_Vp[BATCH * KV_HEADS * (SEQ / 64) * 4096];

// ---------------------------------------------------------------------------
// helpers
// ---------------------------------------------------------------------------
__device__ __forceinline__ void mma_f16(float c[4], const uint32_t a[4], const uint32_t b[2]) {
    asm volatile(
        "mma.sync.aligned.m16n8k16.row.col.f32.f16.f16.f32 "
        "{%0,%1,%2,%3}, {%4,%5,%6,%7}, {%8,%9}, {%0,%1,%2,%3};"
        : "+f"(c[0]), "+f"(c[1]), "+f"(c[2]), "+f"(c[3])
        : "r"(a[0]), "r"(a[1]), "r"(a[2]), "r"(a[3]), "r"(b[0]), "r"(b[1]));
}

__device__ __forceinline__ void cp16(uint32_t dst_smem, const void* src) {
    asm volatile("cp.async.cg.shared.global [%0], [%1], 16;" :: "r"(dst_smem), "l"(src));
}
__device__ __forceinline__ void cp_commit() {
    asm volatile("cp.async.commit_group;");
}
__device__ __forceinline__ void cp_wait_all() {
    asm volatile("cp.async.wait_group 0;");
}
__device__ __forceinline__ void cp_wait_1() {
    asm volatile("cp.async.wait_group 1;");
}

__device__ __forceinline__ uint32_t pack_h2(float lo, float hi) {
    __half2 h = __floats2half2_rn(lo, hi);
    return *(uint32_t*)&h;
}

// ---------------------------------------------------------------------------
// Prep: x -> fp16 (same layout)
// ---------------------------------------------------------------------------
__global__ __launch_bounds__(256) void convert_x_kernel(
    const float4* __restrict__ in, uint2* __restrict__ out, int n4)
{
    int i = blockIdx.x * blockDim.x + threadIdx.x;
    if (i < n4) {
        float4 v = in[i];
        uint2 r;
        r.x = pack_h2(v.x, v.y);
        r.y = pack_h2(v.z, v.w);
        out[i] = r;
    }
}

// Prep: W [K][N] fp32 -> WT [N][K] fp16.  grid (32, K/32, 4)
__global__ __launch_bounds__(256) void transpose_w_kernel(
    const float* __restrict__ Wq, __half* __restrict__ WqT,
    const float* __restrict__ Wk, __half* __restrict__ WkT,
    const float* __restrict__ Wv, __half* __restrict__ WvT,
    const float* __restrict__ Wo, __half* __restrict__ WoT)
{
    const float* in; __half* out; int N;
    switch (blockIdx.z) {
        case 0:  in = Wq; out = WqT; N = D_MODEL; break;
        case 1:  in = Wk; out = WkT; N = D_KV;    break;
        case 2:  in = Wv; out = WvT; N = D_KV;    break;
        default: in = Wo; out = WoT; N = D_MODEL; break;
    }
    int n0 = blockIdx.x * 32;
    if (n0 >= N) return;
    int k0 = blockIdx.y * 32;

    __shared__ float t[32][33];
    int tx = threadIdx.x & 31, ty = threadIdx.x >> 5;
    #pragma unroll
    for (int i = ty; i < 32; i += 8)
        t[i][tx] = in[(size_t)(k0 + i) * N + n0 + tx];
    __syncthreads();
    #pragma unroll
    for (int i = ty; i < 32; i += 8)
        out[(size_t)(n0 + i) * D_MODEL + k0 + tx] = __float2half_rn(t[tx][i]);
}

// ---------------------------------------------------------------------------
// Repack K/V fp16 64x64 head-tiles into m16n8k16 B-fragment order.
// ---------------------------------------------------------------------------
__global__ __launch_bounds__(128) void repack_kv_kernel(
    const __half* __restrict__ K, const __half* __restrict__ V,
    __half* __restrict__ Kp, __half* __restrict__ Vp)
{
    const int kt = blockIdx.x;              // 0..31
    const int bh = blockIdx.y;              // b*4+kh
    const int b = bh >> 2, kh = bh & 3;
    const bool isV = blockIdx.z != 0;
    const __half* src = (isV ? V : K) + ((size_t)(b * SEQ + kt * 64)) * D_KV + kh * HEAD_DIM;
    __half* dst = (isV ? Vp : Kp) + ((size_t)bh * 32 + kt) * 4096;
    const int tid = threadIdx.x;

    #pragma unroll
    for (int p = 0; p < 4; p++) {
        int slot = tid + p * 128;           // 0..511
        int g = slot >> 5, lane = slot & 31;
        int s = g >> 2, na2 = g & 3;
        int gid = lane >> 2, tig = lane & 3;
        uint32_t w[4];
        if (!isV) {
            int r0 = 16 * na2 + gid, r1 = r0 + 8;
            int c0 = 16 * s + 2 * tig, c1 = c0 + 8;
            w[0] = *(const uint32_t*)(src + (size_t)r0 * D_KV + c0);
            w[1] = *(const uint32_t*)(src + (size_t)r0 * D_KV + c1);
            w[2] = *(const uint32_t*)(src + (size_t)r1 * D_KV + c0);
            w[3] = *(const uint32_t*)(src + (size_t)r1 * D_KV + c1);
        } else {
            int kr0 = 16 * s + 2 * tig;
            int vc0 = 16 * na2 + gid, vc1 = vc0 + 8;
            __half2 h;
            h = __halves2half2(src[(size_t)kr0 * D_KV + vc0],
                               src[(size_t)(kr0 + 1) * D_KV + vc0]);
            w[0] = *(uint32_t*)&h;
            h = __halves2half2(src[(size_t)(kr0 + 8) * D_KV + vc0],
                               src[(size_t)(kr0 + 9) * D_KV + vc0]);
            w[1] = *(uint32_t*)&h;
            h = __halves2half2(src[(size_t)kr0 * D_KV + vc1],
                               src[(size_t)(kr0 + 1) * D_KV + vc1]);
            w[2] = *(uint32_t*)&h;
            h = __halves2half2(src[(size_t)(kr0 + 8) * D_KV + vc1],
                               src[(size_t)(kr0 + 9) * D_KV + vc1]);
            w[3] = *(uint32_t*)&h;
        }
        uint4 o = make_uint4(w[0], w[1], w[2], w[3]);
        ((uint4*)dst)[slot] = o;
    }
}

// ---------------------------------------------------------------------------
// FP16 tensor-core GEMM: C[M,N] = A[M,K] @ BT^T + bias.
// CTA 128x128, 256 threads = 8 warps (2x4), warp tile 64x32.
// 16 warps/SM (2 CTAs) for latency hiding; same accumulation order as R14.
// ---------------------------------------------------------------------------
#define GBM 128
#define GBN 128
#define HPW 20                       // row pitch in words
#define A_WORDS (GBM * HPW)          // 2560
#define GSTG (A_WORDS + GBN * HPW)   // 5120 words = 20480 B / stage
#define GSTAGES 3

__device__ __forceinline__ void gemm_issue_tile(
    const __half* __restrict__ A, const __half* __restrict__ BT,
    int row0, int col0, int kt, int st, uint32_t smem_base, int tid)
{
    const int k0 = kt * 32;
    uint32_t abase = smem_base + (uint32_t)st * (GSTG * 4);
    uint32_t bbase = abase + A_WORDS * 4;
    #pragma unroll
    for (int p = 0; p < 2; p++) {
        int id = tid + p * 256;        // 0..511
        int r = id >> 2, c = id & 3;
        cp16(abase + (uint32_t)(r * HPW + c * 4) * 4,
             A + (size_t)(row0 + r) * D_MODEL + k0 + c * 8);
    }
    #pragma unroll
    for (int p = 0; p < 2; p++) {
        int id = tid + p * 256;
        int r = id >> 2, c = id & 3;
        cp16(bbase + (uint32_t)(r * HPW + c * 4) * 4,
             BT + (size_t)(col0 + r) * D_MODEL + k0 + c * 8);
    }
    cp_commit();
}

__device__ __forceinline__ void gemm_body_f16(
    const __half* __restrict__ A, const __half* __restrict__ BT,
    const float* __restrict__ bias, void* __restrict__ C,
    int N, int row0, int col0, bool half_out, uint32_t* sm)
{
    const int tid = threadIdx.x;
    const int lane = tid & 31;
    const int wid = tid >> 5;
    const int warp_m = wid & 1;        // 0..1
    const int warp_n = wid >> 1;       // 0..3
    const int gid = lane >> 2;
    const int tig = lane & 3;

    const uint32_t smem_base = (uint32_t)__cvta_generic_to_shared(sm);

    float acc[4][4][4];
    #pragma unroll
    for (int i = 0; i < 4; i++)
        #pragma unroll
        for (int j = 0; j < 4; j++)
            #pragma unroll
            for (int r = 0; r < 4; r++) acc[i][j][r] = 0.f;

    const int nk = D_MODEL / 32;   // 32
    gemm_issue_tile(A, BT, row0, col0, 0, 0, smem_base, tid);
    gemm_issue_tile(A, BT, row0, col0, 1, 1, smem_base, tid);

    for (int kt = 0; kt < nk; kt++) {
        cp_wait_1();
        __syncthreads();

        if (kt + 2 < nk)
            gemm_issue_tile(A, BT, row0, col0, kt + 2, (kt + 2) % GSTAGES,
                            smem_base, tid);

        const uint32_t* As = sm + (kt % GSTAGES) * GSTG;
        const uint32_t* Bs = As + A_WORDS;

        #pragma unroll
        for (int s = 0; s < 2; s++) {
            uint32_t afr[4][4], bfr[4][2];
            #pragma unroll
            for (int i = 0; i < 4; i++) {
                int mr = warp_m * 64 + i * 16 + gid;
                int o = s * 8 + tig;
                afr[i][0] = As[mr * HPW + o];
                afr[i][1] = As[(mr + 8) * HPW + o];
                afr[i][2] = As[mr * HPW + o + 4];
                afr[i][3] = As[(mr + 8) * HPW + o + 4];
            }
            #pragma unroll
            for (int j = 0; j < 4; j++) {
                int nc = warp_n * 32 + j * 8 + gid;
                int o = s * 8 + tig;
                bfr[j][0] = Bs[nc * HPW + o];
                bfr[j][1] = Bs[nc * HPW + o + 4];
            }
            #pragma unroll
            for (int i = 0; i < 4; i++)
                #pragma unroll
                for (int j = 0; j < 4; j++)
                    mma_f16(acc[i][j], afr[i], bfr[j]);
        }
    }

    #pragma unroll
    for (int i = 0; i < 4; i++) {
        int r = row0 + warp_m * 64 + i * 16 + gid;
        #pragma unroll
        for (int j = 0; j < 4; j++) {
            int c = col0 + warp_n * 32 + j * 8 + tig * 2;
            float b0 = bias[c], b1 = bias[c + 1];
            float o00 = acc[i][j][0] + b0, o01 = acc[i][j][1] + b1;
            float o10 = acc[i][j][2] + b0, o11 = acc[i][j][3] + b1;
            if (half_out) {
                __half* Ch = (__half*)C;
                *(__half2*)(Ch + (size_t)r * N + c) = __floats2half2_rn(o00, o01);
                *(__half2*)(Ch + (size_t)(r + 8) * N + c) = __floats2half2_rn(o10, o11);
            } else {
                float* Cf = (float*)C;
                *(float2*)(Cf + (size_t)r * N + c) = make_float2(o00, o01);
                *(float2*)(Cf + (size_t)(r + 8) * N + c) = make_float2(o10, o11);
            }
        }
    }
}

// Fused QKV projection: bx 0..7 -> Q cols, 8..9 -> K, 10..11 -> V (fp16 out)
__global__ __launch_bounds__(256, 2) void gemm_qkv_f16(
    const __half* __restrict__ X,
    const __half* __restrict__ WqT, const float* __restrict__ bq, __half* __restrict__ Qo,
    const __half* __restrict__ WkT, const float* __restrict__ bk, __half* __restrict__ Ko,
    const __half* __restrict__ WvT, const float* __restrict__ bv, __half* __restrict__ Vo)
{
    extern __shared__ uint32_t sm[];
    const int bx = blockIdx.x;
    const int row0 = blockIdx.y * GBM;

    const __half* BT; const float* bias; __half* C; int N, col0;
    if (bx < 8)       { BT = WqT; bias = bq; C = Qo; N = D_MODEL; col0 = bx * GBN;        }
    else if (bx < 10) { BT = WkT; bias = bk; C = Ko; N = D_KV;    col0 = (bx - 8) * GBN;  }
    else              { BT = WvT; bias = bv; C = Vo; N = D_KV;    col0 = (bx - 10) * GBN; }

    gemm_body_f16(X, BT, bias, C, N, row0, col0, true, sm);
}

// Output projection (fp32 out)
__global__ __launch_bounds__(256, 2) void gemm_out_f16(
    const __half* __restrict__ A, const __half* __restrict__ WoT,
    const float* __restrict__ bo, float* __restrict__ C)
{
    extern __shared__ uint32_t sm[];
    gemm_body_f16(A, WoT, bo, C, D_MODEL, blockIdx.y * GBM, blockIdx.x * GBN, false, sm);
}

// ---------------------------------------------------------------------------
// Flash attention (causal, GQA), fp16 m16n8k16 — unchanged from R14.
// ---------------------------------------------------------------------------
#define FA_STG 4096   // words/stage: K 2048 + V 2048 (16 KB)

__global__ __launch_bounds__(128, 4) void fa_f16_kernel(
    const __half* __restrict__ Qh, const __half* __restrict__ Kpk,
    const __half* __restrict__ Vpk, __half* __restrict__ Oh)
{
    extern __shared__ uint32_t smu[];   // [2][FA_STG]

    const int bh = blockIdx.x;
    const int b  = bh >> 4;
    const int h  = bh & 15;
    const int kh = h >> 2;
    const int qt = (SEQ / 64 - 1) - blockIdx.y;   // LPT: heavy tiles first
    const int q0 = qt * 64;
    const int tid = threadIdx.x;
    const int lane = tid & 31;
    const int w = tid >> 5;
    const int gid = lane >> 2;
    const int tig = lane & 3;

    const uint32_t smem_base = (uint32_t)__cvta_generic_to_shared(smu);

    const __half* Kt = Kpk + ((size_t)(b * 4 + kh) * 32) * 4096;
    const __half* Vt = Vpk + ((size_t)(b * 4 + kh) * 32) * 4096;

    auto issue_tile = [&](int kt, int st) {
        const __half* Kg = Kt + (size_t)kt * 4096;
        const __half* Vg = Vt + (size_t)kt * 4096;
        uint32_t kbase = smem_base + (uint32_t)st * (FA_STG * 4);
        uint32_t vbase = kbase + 2048 * 4;
        #pragma unroll
        for (int p = 0; p < 4; p++) {
            int id = tid + p * 128;   // 0..511 16B chunks
            cp16(kbase + (uint32_t)id * 16, Kg + (size_t)id * 8);
            cp16(vbase + (uint32_t)id * 16, Vg + (size_t)id * 8);
        }
        cp_commit();
    };

    issue_tile(0, 0);

    // Q fragments: rows q0+w*16+{gid,gid+8}; scale 1/8 exact in fp16
    uint32_t qfr[4][4];
    {
        const __half* Qg = Qh + ((size_t)(b * SEQ + q0 + w * 16)) * D_MODEL + h * HEAD_DIM;
        const __half2 sc = __float2half2_rn(0.125f);
        #pragma unroll
        for (int s = 0; s < 4; s++) {
            int c0 = 16 * s + 2 * tig;
            __half2 a0 = __hmul2(*(const __half2*)(Qg + (size_t)gid * D_MODEL + c0), sc);
            __half2 a1 = __hmul2(*(const __half2*)(Qg + (size_t)(gid + 8) * D_MODEL + c0), sc);
            __half2 a2 = __hmul2(*(const __half2*)(Qg + (size_t)gid * D_MODEL + c0 + 8), sc);
            __half2 a3 = __hmul2(*(const __half2*)(Qg + (size_t)(gid + 8) * D_MODEL + c0 + 8), sc);
            qfr[s][0] = *(uint32_t*)&a0;
            qfr[s][1] = *(uint32_t*)&a1;
            qfr[s][2] = *(uint32_t*)&a2;
            qfr[s][3] = *(uint32_t*)&a3;
        }
    }

    float m0 = -INFINITY, m1 = -INFINITY, l0 = 0.f, l1 = 0.f;
    float oacc[8][4];
    #pragma unroll
    for (int na = 0; na < 8; na++)
        #pragma unroll
        for (int c = 0; c < 4; c++) oacc[na][c] = 0.f;

    const int fidx = (gid * 4 + tig) * 4;

    for (int kt = 0; kt <= qt; kt++) {
        cp_wait_all();
        __syncthreads();

        if (kt < qt) issue_tile(kt + 1, (kt + 1) & 1);

        const uint32_t* Ks = smu + (size_t)(kt & 1) * FA_STG;
        const uint32_t* Vs = Ks + 2048;

        // ---- S = Q K^T ----
        float sacc[8][4];
        #pragma unroll
        for (int na = 0; na < 8; na++)
            #pragma unroll
            for (int c = 0; c < 4; c++) sacc[na][c] = 0.f;

        #pragma unroll
        for (int s = 0; s < 4; s++) {
            #pragma unroll
            for (int na2 = 0; na2 < 4; na2++) {
                uint4 k4 = *(const uint4*)(Ks + (s * 4 + na2) * 128 + fidx);
                uint32_t b0[2] = { k4.x, k4.y };
                uint32_t b1[2] = { k4.z, k4.w };
                mma_f16(sacc[2 * na2],     qfr[s], b0);
                mma_f16(sacc[2 * na2 + 1], qfr[s], b1);
            }
        }

        // ---- causal mask on diagonal tile ----
        if (kt == qt) {
            int rbase = w * 16 + gid;
            #pragma unroll
            for (int na = 0; na < 8; na++) {
                int cbase = na * 8 + tig * 2;
                if (cbase     > rbase)     sacc[na][0] = -INFINITY;
                if (cbase + 1 > rbase)     sacc[na][1] = -INFINITY;
                if (cbase     > rbase + 8) sacc[na][2] = -INFINITY;
                if (cbase + 1 > rbase + 8) sacc[na][3] = -INFINITY;
            }
        }

        // ---- online softmax (regs + 4-lane shfl reductions) ----
        float tm0 = -INFINITY, tm1 = -INFINITY;
        #pragma unroll
        for (int na = 0; na < 8; na++) {
            tm0 = fmaxf(tm0, fmaxf(sacc[na][0], sacc[na][1]));
            tm1 = fmaxf(tm1, fmaxf(sacc[na][2], sacc[na][3]));
        }
        tm0 = fmaxf(tm0, __shfl_xor_sync(0xffffffffu, tm0, 1));
        tm0 = fmaxf(tm0, __shfl_xor_sync(0xffffffffu, tm0, 2));
        tm1 = fmaxf(tm1, __shfl_xor_sync(0xffffffffu, tm1, 1));
        tm1 = fmaxf(tm1, __shfl_xor_sync(0xffffffffu, tm1, 2));

        float mn0 = fmaxf(m0, tm0), mn1 = fmaxf(m1, tm1);
        float ts0 = 0.f, ts1 = 0.f;
        #pragma unroll
        for (int na = 0; na < 8; na++) {
            sacc[na][0] = __expf(sacc[na][0] - mn0); ts0 += sacc[na][0];
            sacc[na][1] = __expf(sacc[na][1] - mn0); ts0 += sacc[na][1];
            sacc[na][2] = __expf(sacc[na][2] - mn1); ts1 += sacc[na][2];
            sacc[na][3] = __expf(sacc[na][3] - mn1); ts1 += sacc[na][3];
        }
        ts0 += __shfl_xor_sync(0xffffffffu, ts0, 1);
        ts0 += __shfl_xor_sync(0xffffffffu, ts0, 2);
        ts1 += __shfl_xor_sync(0xffffffffu, ts1, 1);
        ts1 += __shfl_xor_sync(0xffffffffu, ts1, 2);

        float a0 = __expf(m0 - mn0), a1 = __expf(m1 - mn1);
        l0 = l0 * a0 + ts0;
        l1 = l1 * a1 + ts1;
        m0 = mn0; m1 = mn1;

        #pragma unroll
        for (int na = 0; na < 8; na++) {
            oacc[na][0] *= a0; oacc[na][1] *= a0;
            oacc[na][2] *= a1; oacc[na][3] *= a1;
        }

        // ---- O += P V : A-frag == C-frag layout, just pack to half2 ----
        #pragma unroll
        for (int s = 0; s < 4; s++) {
            uint32_t ap[4];
            ap[0] = pack_h2(sacc[2 * s][0],     sacc[2 * s][1]);
            ap[1] = pack_h2(sacc[2 * s][2],     sacc[2 * s][3]);
            ap[2] = pack_h2(sacc[2 * s + 1][0], sacc[2 * s + 1][1]);
            ap[3] = pack_h2(sacc[2 * s + 1][2], sacc[2 * s + 1][3]);
            #pragma unroll
            for (int na2 = 0; na2 < 4; na2++) {
                uint4 v4 = *(const uint4*)(Vs + (s * 4 + na2) * 128 + fidx);
                uint32_t b0[2] = { v4.x, v4.y };
                uint32_t b1[2] = { v4.z, v4.w };
                mma_f16(oacc[2 * na2],     ap, b0);
                mma_f16(oacc[2 * na2 + 1], ap, b1);
            }
        }
    }

    // ---- normalize + write O (fp16, consumed by out-proj) ----
    float inv0 = 1.0f / l0, inv1 = 1.0f / l1;
    __half* Og = Oh + ((size_t)(b * SEQ + q0)) * D_MODEL + h * HEAD_DIM;
    int r = w * 16 + gid;
    #pragma unroll
    for (int na = 0; na < 8; na++) {
        int c = na * 8 + tig * 2;
        *(__half2*)(Og + (size_t)r * D_MODEL + c) =
            __floats2half2_rn(oacc[na][0] * inv0, oacc[na][1] * inv0);
        *(__half2*)(Og + (size_t)(r + 8) * D_MODEL + c) =
            __floats2half2_rn(oacc[na][2] * inv1, oacc[na][3] * inv1);
    }
}

// ---------------------------------------------------------------------------
// Launch
// ---------------------------------------------------------------------------
extern "C" void kernel_launch(void* const* d_in, const int* in_sizes, int n_in,
                              void* d_out, int out_size)
{
    const float* x  = (const float*)d_in[0];
    const float* Wq = (const float*)d_in[1];
    const float* bq = (const float*)d_in[2];
    const float* Wk = (const float*)d_in[3];
    const float* bk = (const float*)d_in[4];
    const float* Wv = (const float*)d_in[5];
    const float* bv = (const float*)d_in[6];
    const float* Wo = (const float*)d_in[7];
    const float* bo = (const float*)d_in[8];
    // d_in[9] = mask (causal; computed implicitly)
    float* out = (float*)d_out;

    __half *Xh, *WqT, *WkT, *WvT, *WoT, *Qh, *Kh, *Vh, *Oh, *Kpp, *Vpp;
    cudaGetSymbolAddress((void**)&Xh,  g_Xh);
    cudaGetSymbolAddress((void**)&WqT, g_WqT);
    cudaGetSymbolAddress((void**)&WkT, g_WkT);
    cudaGetSymbolAddress((void**)&WvT, g_WvT);
    cudaGetSymbolAddress((void**)&WoT, g_WoT);
    cudaGetSymbolAddress((void**)&Qh,  g_Qh);
    cudaGetSymbolAddress((void**)&Kh,  g_Kh);
    cudaGetSymbolAddress((void**)&Vh,  g_Vh);
    cudaGetSymbolAddress((void**)&Oh,  g_Oh);
    cudaGetSymbolAddress((void**)&Kpp, g_Kp);
    cudaGetSymbolAddress((void**)&Vpp, g_Vp);

    // prep: x -> fp16; W -> transposed fp16
    {
        int n4 = BS * D_MODEL / 4;
        convert_x_kernel<<<(n4 + 255) / 256, 256>>>((const float4*)x, (uint2*)Xh, n4);
        dim3 gt(32, 32, 4);
        transpose_w_kernel<<<gt, 256>>>(Wq, WqT, Wk, WkT, Wv, WvT, Wo, WoT);
    }

    size_t gemm_smem = (size_t)GSTAGES * GSTG * sizeof(uint32_t);   // 61440 B

    // fused QKV projection (fp16 HMMA, 8 warps/CTA)
    {
        cudaFuncSetAttribute(gemm_qkv_f16, cudaFuncAttributeMaxDynamicSharedMemorySize,
                             (int)gemm_smem);
        dim3 g(12, BS / GBM);
        gemm_qkv_f16<<<g, 256, gemm_smem>>>(Xh, WqT, bq, Qh, WkT, bk, Kh, WvT, bv, Vh);
    }

    // repack K/V into fp16 fragment order
    {
        dim3 g(SEQ / 64, BATCH * KV_HEADS, 2);
        repack_kv_kernel<<<g, 128>>>(Kh, Vh, Kpp, Vpp);
    }

    // flash attention (fp16 HMMA)
    {
        size_t smem = (size_t)(2 * FA_STG) * sizeof(uint32_t);   // 32768 B
        cudaFuncSetAttribute(fa_f16_kernel, cudaFuncAttributeMaxDynamicSharedMemorySize,
                             (int)smem);
        dim3 g(BATCH * N_HEADS, SEQ / 64);
        fa_f16_kernel<<<g, 128, smem>>>(Qh, Kpp, Vpp, Oh);
    }

    // output projection (fp16 HMMA, fp32 out, 8 warps/CTA)
    {
        cudaFuncSetAttribute(gemm_out_f16, cudaFuncAttributeMaxDynamicSharedMemorySize,
                             (int)gemm_smem);
        dim3 go(D_MODEL / GBN, BS / GBM);
        gemm_out_f16<<<go, 256, gemm_smem>>>(Oh, WoT, bo, out);
    }
}

// round 17
// speedup vs baseline: 1.0516x; 1.0516x over previous
#include <cuda_runtime.h>
#include <cuda_fp16.h>
#include <math.h>
#include <stdint.h>

// Problem constants
#define D_MODEL 1024
#define N_HEADS 16
#define N_GROUPS 4
#define HEAD_DIM 64
#define KV_HEADS 4
#define D_KV 256
#define BATCH 2
#define SEQ 2048
#define BS (BATCH * SEQ)   // 4096

// Scratch buffers (device globals)
__device__ __half g_Xh[BS * D_MODEL];        // fp16 x
__device__ __half g_WqT[D_MODEL * D_MODEL];  // [N][K] fp16
__device__ __half g_WkT[D_KV * D_MODEL];
__device__ __half g_WvT[D_KV * D_MODEL];
__device__ __half g_WoT[D_MODEL * D_MODEL];
__device__ __half g_Qh[BS * D_MODEL];
__device__ __half g_Kh[BS * D_KV];
__device__ __half g_Vh[BS * D_KV];
__device__ __half g_Oh[BS * D_MODEL];
// fragment-packed K/V tiles: [b*4+kh][kt][4096 halves]
__device__ __half g_Kp[BATCH * KV_HEADS * (SEQ / 64) * 4096];
__device__ __half g_Vp[BATCH * KV_HEADS * (SEQ / 64) * 4096];

// ---------------------------------------------------------------------------
// helpers
// ---------------------------------------------------------------------------
__device__ __forceinline__ void mma_f16(float c[4], const uint32_t a[4], const uint32_t b[2]) {
    asm volatile(
        "mma.sync.aligned.m16n8k16.row.col.f32.f16.f16.f32 "
        "{%0,%1,%2,%3}, {%4,%5,%6,%7}, {%8,%9}, {%0,%1,%2,%3};"
        : "+f"(c[0]), "+f"(c[1]), "+f"(c[2]), "+f"(c[3])
        : "r"(a[0]), "r"(a[1]), "r"(a[2]), "r"(a[3]), "r"(b[0]), "r"(b[1]));
}

__device__ __forceinline__ void cp16(uint32_t dst_smem, const void* src) {
    asm volatile("cp.async.cg.shared.global [%0], [%1], 16;" :: "r"(dst_smem), "l"(src));
}
__device__ __forceinline__ void cp_commit() {
    asm volatile("cp.async.commit_group;");
}
__device__ __forceinline__ void cp_wait_all() {
    asm volatile("cp.async.wait_group 0;");
}
__device__ __forceinline__ void cp_wait_1() {
    asm volatile("cp.async.wait_group 1;");
}

__device__ __forceinline__ uint32_t pack_h2(float lo, float hi) {
    __half2 h = __floats2half2_rn(lo, hi);
    return *(uint32_t*)&h;
}

// 2^x on packed fp16 pair (one MUFU op for two values)
__device__ __forceinline__ uint32_t h2exp2_u32(uint32_t x) {
    uint32_t r;
    asm("ex2.approx.f16x2 %0, %1;" : "=r"(r) : "r"(x));
    return r;
}

// ---------------------------------------------------------------------------
// Prep: x -> fp16 (same layout)
// ---------------------------------------------------------------------------
__global__ __launch_bounds__(256) void convert_x_kernel(
    const float4* __restrict__ in, uint2* __restrict__ out, int n4)
{
    int i = blockIdx.x * blockDim.x + threadIdx.x;
    if (i < n4) {
        float4 v = in[i];
        uint2 r;
        r.x = pack_h2(v.x, v.y);
        r.y = pack_h2(v.z, v.w);
        out[i] = r;
    }
}

// Prep: W [K][N] fp32 -> WT [N][K] fp16.  grid (32, K/32, 4)
__global__ __launch_bounds__(256) void transpose_w_kernel(
    const float* __restrict__ Wq, __half* __restrict__ WqT,
    const float* __restrict__ Wk, __half* __restrict__ WkT,
    const float* __restrict__ Wv, __half* __restrict__ WvT,
    const float* __restrict__ Wo, __half* __restrict__ WoT)
{
    const float* in; __half* out; int N;
    switch (blockIdx.z) {
        case 0:  in = Wq; out = WqT; N = D_MODEL; break;
        case 1:  in = Wk; out = WkT; N = D_KV;    break;
        case 2:  in = Wv; out = WvT; N = D_KV;    break;
        default: in = Wo; out = WoT; N = D_MODEL; break;
    }
    int n0 = blockIdx.x * 32;
    if (n0 >= N) return;
    int k0 = blockIdx.y * 32;

    __shared__ float t[32][33];
    int tx = threadIdx.x & 31, ty = threadIdx.x >> 5;
    #pragma unroll
    for (int i = ty; i < 32; i += 8)
        t[i][tx] = in[(size_t)(k0 + i) * N + n0 + tx];
    __syncthreads();
    #pragma unroll
    for (int i = ty; i < 32; i += 8)
        out[(size_t)(n0 + i) * D_MODEL + k0 + tx] = __float2half_rn(t[tx][i]);
}

// ---------------------------------------------------------------------------
// Repack K/V fp16 64x64 head-tiles into m16n8k16 B-fragment order.
// ---------------------------------------------------------------------------
__global__ __launch_bounds__(128) void repack_kv_kernel(
    const __half* __restrict__ K, const __half* __restrict__ V,
    __half* __restrict__ Kp, __half* __restrict__ Vp)
{
    const int kt = blockIdx.x;              // 0..31
    const int bh = blockIdx.y;              // b*4+kh
    const int b = bh >> 2, kh = bh & 3;
    const bool isV = blockIdx.z != 0;
    const __half* src = (isV ? V : K) + ((size_t)(b * SEQ + kt * 64)) * D_KV + kh * HEAD_DIM;
    __half* dst = (isV ? Vp : Kp) + ((size_t)bh * 32 + kt) * 4096;
    const int tid = threadIdx.x;

    #pragma unroll
    for (int p = 0; p < 4; p++) {
        int slot = tid + p * 128;           // 0..511
        int g = slot >> 5, lane = slot & 31;
        int s = g >> 2, na2 = g & 3;
        int gid = lane >> 2, tig = lane & 3;
        uint32_t w[4];
        if (!isV) {
            int r0 = 16 * na2 + gid, r1 = r0 + 8;
            int c0 = 16 * s + 2 * tig, c1 = c0 + 8;
            w[0] = *(const uint32_t*)(src + (size_t)r0 * D_KV + c0);
            w[1] = *(const uint32_t*)(src + (size_t)r0 * D_KV + c1);
            w[2] = *(const uint32_t*)(src + (size_t)r1 * D_KV + c0);
            w[3] = *(const uint32_t*)(src + (size_t)r1 * D_KV + c1);
        } else {
            int kr0 = 16 * s + 2 * tig;
            int vc0 = 16 * na2 + gid, vc1 = vc0 + 8;
            __half2 h;
            h = __halves2half2(src[(size_t)kr0 * D_KV + vc0],
                               src[(size_t)(kr0 + 1) * D_KV + vc0]);
            w[0] = *(uint32_t*)&h;
            h = __halves2half2(src[(size_t)(kr0 + 8) * D_KV + vc0],
                               src[(size_t)(kr0 + 9) * D_KV + vc0]);
            w[1] = *(uint32_t*)&h;
            h = __halves2half2(src[(size_t)kr0 * D_KV + vc1],
                               src[(size_t)(kr0 + 1) * D_KV + vc1]);
            w[2] = *(uint32_t*)&h;
            h = __halves2half2(src[(size_t)(kr0 + 8) * D_KV + vc1],
                               src[(size_t)(kr0 + 9) * D_KV + vc1]);
            w[3] = *(uint32_t*)&h;
        }
        uint4 o = make_uint4(w[0], w[1], w[2], w[3]);
        ((uint4*)dst)[slot] = o;
    }
}

// ---------------------------------------------------------------------------
// FP16 tensor-core GEMM (R14 config): C[M,N] = A[M,K] @ BT^T + bias.
// CTA 128x128, 128 threads (2x2 warps, 64x64 warp tiles), cp.async 3-stage.
// ---------------------------------------------------------------------------
#define GBM 128
#define GBN 128
#define HPW 20                       // row pitch in words
#define A_WORDS (GBM * HPW)          // 2560
#define GSTG (A_WORDS + GBN * HPW)   // 5120 words = 20480 B / stage
#define GSTAGES 3

__device__ __forceinline__ void gemm_issue_tile(
    const __half* __restrict__ A, const __half* __restrict__ BT,
    int row0, int col0, int kt, int st, uint32_t smem_base, int tid)
{
    const int k0 = kt * 32;
    uint32_t abase = smem_base + (uint32_t)st * (GSTG * 4);
    uint32_t bbase = abase + A_WORDS * 4;
    #pragma unroll
    for (int p = 0; p < 4; p++) {
        int id = tid + p * 128;        // 0..511
        int r = id >> 2, c = id & 3;
        cp16(abase + (uint32_t)(r * HPW + c * 4) * 4,
             A + (size_t)(row0 + r) * D_MODEL + k0 + c * 8);
    }
    #pragma unroll
    for (int p = 0; p < 4; p++) {
        int id = tid + p * 128;
        int r = id >> 2, c = id & 3;
        cp16(bbase + (uint32_t)(r * HPW + c * 4) * 4,
             BT + (size_t)(col0 + r) * D_MODEL + k0 + c * 8);
    }
    cp_commit();
}

__device__ __forceinline__ void gemm_body_f16(
    const __half* __restrict__ A, const __half* __restrict__ BT,
    const float* __restrict__ bias, void* __restrict__ C,
    int N, int row0, int col0, bool half_out, uint32_t* sm)
{
    const int tid = threadIdx.x;
    const int lane = tid & 31;
    const int wid = tid >> 5;
    const int warp_m = wid & 1;
    const int warp_n = wid >> 1;
    const int gid = lane >> 2;
    const int tig = lane & 3;

    const uint32_t smem_base = (uint32_t)__cvta_generic_to_shared(sm);

    float acc[4][8][4];
    #pragma unroll
    for (int i = 0; i < 4; i++)
        #pragma unroll
        for (int j = 0; j < 8; j++)
            #pragma unroll
            for (int r = 0; r < 4; r++) acc[i][j][r] = 0.f;

    const int nk = D_MODEL / 32;   // 32
    gemm_issue_tile(A, BT, row0, col0, 0, 0, smem_base, tid);
    gemm_issue_tile(A, BT, row0, col0, 1, 1, smem_base, tid);

    for (int kt = 0; kt < nk; kt++) {
        cp_wait_1();
        __syncthreads();

        if (kt + 2 < nk)
            gemm_issue_tile(A, BT, row0, col0, kt + 2, (kt + 2) % GSTAGES,
                            smem_base, tid);

        const uint32_t* As = sm + (kt % GSTAGES) * GSTG;
        const uint32_t* Bs = As + A_WORDS;

        #pragma unroll
        for (int s = 0; s < 2; s++) {
            uint32_t afr[4][4], bfr[8][2];
            #pragma unroll
            for (int i = 0; i < 4; i++) {
                int mr = warp_m * 64 + i * 16 + gid;
                int o = s * 8 + tig;
                afr[i][0] = As[mr * HPW + o];
                afr[i][1] = As[(mr + 8) * HPW + o];
                afr[i][2] = As[mr * HPW + o + 4];
                afr[i][3] = As[(mr + 8) * HPW + o + 4];
            }
            #pragma unroll
            for (int j = 0; j < 8; j++) {
                int nc = warp_n * 64 + j * 8 + gid;
                int o = s * 8 + tig;
                bfr[j][0] = Bs[nc * HPW + o];
                bfr[j][1] = Bs[nc * HPW + o + 4];
            }
            #pragma unroll
            for (int i = 0; i < 4; i++)
                #pragma unroll
                for (int j = 0; j < 8; j++)
                    mma_f16(acc[i][j], afr[i], bfr[j]);
        }
    }

    #pragma unroll
    for (int i = 0; i < 4; i++) {
        int r = row0 + warp_m * 64 + i * 16 + gid;
        #pragma unroll
        for (int j = 0; j < 8; j++) {
            int c = col0 + warp_n * 64 + j * 8 + tig * 2;
            float b0 = bias[c], b1 = bias[c + 1];
            float o00 = acc[i][j][0] + b0, o01 = acc[i][j][1] + b1;
            float o10 = acc[i][j][2] + b0, o11 = acc[i][j][3] + b1;
            if (half_out) {
                __half* Ch = (__half*)C;
                *(__half2*)(Ch + (size_t)r * N + c) = __floats2half2_rn(o00, o01);
                *(__half2*)(Ch + (size_t)(r + 8) * N + c) = __floats2half2_rn(o10, o11);
            } else {
                float* Cf = (float*)C;
                *(float2*)(Cf + (size_t)r * N + c) = make_float2(o00, o01);
                *(float2*)(Cf + (size_t)(r + 8) * N + c) = make_float2(o10, o11);
            }
        }
    }
}

// Fused QKV projection: bx 0..7 -> Q cols, 8..9 -> K, 10..11 -> V (fp16 out)
__global__ __launch_bounds__(128, 2) void gemm_qkv_f16(
    const __half* __restrict__ X,
    const __half* __restrict__ WqT, const float* __restrict__ bq, __half* __restrict__ Qo,
    const __half* __restrict__ WkT, const float* __restrict__ bk, __half* __restrict__ Ko,
    const __half* __restrict__ WvT, const float* __restrict__ bv, __half* __restrict__ Vo)
{
    extern __shared__ uint32_t sm[];
    const int bx = blockIdx.x;
    const int row0 = blockIdx.y * GBM;

    const __half* BT; const float* bias; __half* C; int N, col0;
    if (bx < 8)       { BT = WqT; bias = bq; C = Qo; N = D_MODEL; col0 = bx * GBN;        }
    else if (bx < 10) { BT = WkT; bias = bk; C = Ko; N = D_KV;    col0 = (bx - 8) * GBN;  }
    else              { BT = WvT; bias = bv; C = Vo; N = D_KV;    col0 = (bx - 10) * GBN; }

    gemm_body_f16(X, BT, bias, C, N, row0, col0, true, sm);
}

// Output projection (fp32 out)
__global__ __launch_bounds__(128, 2) void gemm_out_f16(
    const __half* __restrict__ A, const __half* __restrict__ WoT,
    const float* __restrict__ bo, float* __restrict__ C)
{
    extern __shared__ uint32_t sm[];
    gemm_body_f16(A, WoT, bo, C, D_MODEL, blockIdx.y * GBM, blockIdx.x * GBN, false, sm);
}

// ---------------------------------------------------------------------------
// Flash attention (causal, GQA), fp16 m16n8k16.
// Scores in log2 domain (log2e folded into Q scale); P = ex2.approx.f16x2
// (one MUFU per pair, output directly in A-fragment fp16 layout).
// ---------------------------------------------------------------------------
#define FA_STG 4096   // words/stage: K 2048 + V 2048 (16 KB)

__global__ __launch_bounds__(128, 4) void fa_f16_kernel(
    const __half* __restrict__ Qh, const __half* __restrict__ Kpk,
    const __half* __restrict__ Vpk, __half* __restrict__ Oh)
{
    extern __shared__ uint32_t smu[];   // [2][FA_STG]

    const int bh = blockIdx.x;
    const int b  = bh >> 4;
    const int h  = bh & 15;
    const int kh = h >> 2;
    const int qt = (SEQ / 64 - 1) - blockIdx.y;   // LPT: heavy tiles first
    const int q0 = qt * 64;
    const int tid = threadIdx.x;
    const int lane = tid & 31;
    const int w = tid >> 5;
    const int gid = lane >> 2;
    const int tig = lane & 3;

    const uint32_t smem_base = (uint32_t)__cvta_generic_to_shared(smu);

    const __half* Kt = Kpk + ((size_t)(b * 4 + kh) * 32) * 4096;
    const __half* Vt = Vpk + ((size_t)(b * 4 + kh) * 32) * 4096;

    auto issue_tile = [&](int kt, int st) {
        const __half* Kg = Kt + (size_t)kt * 4096;
        const __half* Vg = Vt + (size_t)kt * 4096;
        uint32_t kbase = smem_base + (uint32_t)st * (FA_STG * 4);
        uint32_t vbase = kbase + 2048 * 4;
        #pragma unroll
        for (int p = 0; p < 4; p++) {
            int id = tid + p * 128;   // 0..511 16B chunks
            cp16(kbase + (uint32_t)id * 16, Kg + (size_t)id * 8);
            cp16(vbase + (uint32_t)id * 16, Vg + (size_t)id * 8);
        }
        cp_commit();
    };

    issue_tile(0, 0);

    // Q fragments: scale = (1/8)*log2(e) folded in -> scores in log2 domain
    uint32_t qfr[4][4];
    {
        const __half* Qg = Qh + ((size_t)(b * SEQ + q0 + w * 16)) * D_MODEL + h * HEAD_DIM;
        const __half2 sc = __float2half2_rn(0.125f * 1.4426950408889634f);
        #pragma unroll
        for (int s = 0; s < 4; s++) {
            int c0 = 16 * s + 2 * tig;
            __half2 a0 = __hmul2(*(const __half2*)(Qg + (size_t)gid * D_MODEL + c0), sc);
            __half2 a1 = __hmul2(*(const __half2*)(Qg + (size_t)(gid + 8) * D_MODEL + c0), sc);
            __half2 a2 = __hmul2(*(const __half2*)(Qg + (size_t)gid * D_MODEL + c0 + 8), sc);
            __half2 a3 = __hmul2(*(const __half2*)(Qg + (size_t)(gid + 8) * D_MODEL + c0 + 8), sc);
            qfr[s][0] = *(uint32_t*)&a0;
            qfr[s][1] = *(uint32_t*)&a1;
            qfr[s][2] = *(uint32_t*)&a2;
            qfr[s][3] = *(uint32_t*)&a3;
        }
    }

    float m0 = -INFINITY, m1 = -INFINITY, l0 = 0.f, l1 = 0.f;
    float oacc[8][4];
    #pragma unroll
    for (int na = 0; na < 8; na++)
        #pragma unroll
        for (int c = 0; c < 4; c++) oacc[na][c] = 0.f;

    const int fidx = (gid * 4 + tig) * 4;

    for (int kt = 0; kt <= qt; kt++) {
        cp_wait_all();
        __syncthreads();

        if (kt < qt) issue_tile(kt + 1, (kt + 1) & 1);

        const uint32_t* Ks = smu + (size_t)(kt & 1) * FA_STG;
        const uint32_t* Vs = Ks + 2048;

        // ---- S = Q K^T (log2-domain scores) ----
        float sacc[8][4];
        #pragma unroll
        for (int na = 0; na < 8; na++)
            #pragma unroll
            for (int c = 0; c < 4; c++) sacc[na][c] = 0.f;

        #pragma unroll
        for (int s = 0; s < 4; s++) {
            #pragma unroll
            for (int na2 = 0; na2 < 4; na2++) {
                uint4 k4 = *(const uint4*)(Ks + (s * 4 + na2) * 128 + fidx);
                uint32_t b0[2] = { k4.x, k4.y };
                uint32_t b1[2] = { k4.z, k4.w };
                mma_f16(sacc[2 * na2],     qfr[s], b0);
                mma_f16(sacc[2 * na2 + 1], qfr[s], b1);
            }
        }

        // ---- causal mask on diagonal tile ----
        if (kt == qt) {
            int rbase = w * 16 + gid;
            #pragma unroll
            for (int na = 0; na < 8; na++) {
                int cbase = na * 8 + tig * 2;
                if (cbase     > rbase)     sacc[na][0] = -INFINITY;
                if (cbase + 1 > rbase)     sacc[na][1] = -INFINITY;
                if (cbase     > rbase + 8) sacc[na][2] = -INFINITY;
                if (cbase + 1 > rbase + 8) sacc[na][3] = -INFINITY;
            }
        }

        // ---- online softmax (log2 domain; P via ex2.approx.f16x2) ----
        float tm0 = -INFINITY, tm1 = -INFINITY;
        #pragma unroll
        for (int na = 0; na < 8; na++) {
            tm0 = fmaxf(tm0, fmaxf(sacc[na][0], sacc[na][1]));
            tm1 = fmaxf(tm1, fmaxf(sacc[na][2], sacc[na][3]));
        }
        tm0 = fmaxf(tm0, __shfl_xor_sync(0xffffffffu, tm0, 1));
        tm0 = fmaxf(tm0, __shfl_xor_sync(0xffffffffu, tm0, 2));
        tm1 = fmaxf(tm1, __shfl_xor_sync(0xffffffffu, tm1, 1));
        tm1 = fmaxf(tm1, __shfl_xor_sync(0xffffffffu, tm1, 2));

        float mn0 = fmaxf(m0, tm0), mn1 = fmaxf(m1, tm1);

        // P = 2^(s - mn) computed pairwise in fp16; pw[na][0]=row gid pair,
        // pw[na][1]=row gid+8 pair (exact A-fragment words for PV)
        uint32_t pw[8][2];
        float ts0 = 0.f, ts1 = 0.f;
        #pragma unroll
        for (int na = 0; na < 8; na++) {
            pw[na][0] = h2exp2_u32(pack_h2(sacc[na][0] - mn0, sacc[na][1] - mn0));
            pw[na][1] = h2exp2_u32(pack_h2(sacc[na][2] - mn1, sacc[na][3] - mn1));
            float2 f0 = __half22float2(*(__half2*)&pw[na][0]);
            float2 f1 = __half22float2(*(__half2*)&pw[na][1]);
            ts0 += f0.x + f0.y;
            ts1 += f1.x + f1.y;
        }
        ts0 += __shfl_xor_sync(0xffffffffu, ts0, 1);
        ts0 += __shfl_xor_sync(0xffffffffu, ts0, 2);
        ts1 += __shfl_xor_sync(0xffffffffu, ts1, 1);
        ts1 += __shfl_xor_sync(0xffffffffu, ts1, 2);

        float a0 = exp2f(m0 - mn0), a1 = exp2f(m1 - mn1);
        l0 = l0 * a0 + ts0;
        l1 = l1 * a1 + ts1;
        m0 = mn0; m1 = mn1;

        #pragma unroll
        for (int na = 0; na < 8; na++) {
            oacc[na][0] *= a0; oacc[na][1] *= a0;
            oacc[na][2] *= a1; oacc[na][3] *= a1;
        }

        // ---- O += P V : P words feed A-fragments directly ----
        #pragma unroll
        for (int s = 0; s < 4; s++) {
            uint32_t ap[4] = { pw[2 * s][0], pw[2 * s][1],
                               pw[2 * s + 1][0], pw[2 * s + 1][1] };
            #pragma unroll
            for (int na2 = 0; na2 < 4; na2++) {
                uint4 v4 = *(const uint4*)(Vs + (s * 4 + na2) * 128 + fidx);
                uint32_t b0[2] = { v4.x, v4.y };
                uint32_t b1[2] = { v4.z, v4.w };
                mma_f16(oacc[2 * na2],     ap, b0);
                mma_f16(oacc[2 * na2 + 1], ap, b1);
            }
        }
    }

    // ---- normalize + write O (fp16, consumed by out-proj) ----
    float inv0 = 1.0f / l0, inv1 = 1.0f / l1;
    __half* Og = Oh + ((size_t)(b * SEQ + q0)) * D_MODEL + h * HEAD_DIM;
    int r = w * 16 + gid;
    #pragma unroll
    for (int na = 0; na < 8; na++) {
        int c = na * 8 + tig * 2;
        *(__half2*)(Og + (size_t)r * D_MODEL + c) =
            __floats2half2_rn(oacc[na][0] * inv0, oacc[na][1] * inv0);
        *(__half2*)(Og + (size_t)(r + 8) * D_MODEL + c) =
            __floats2half2_rn(oacc[na][2] * inv1, oacc[na][3] * inv1);
    }
}

// ---------------------------------------------------------------------------
// Launch
// ---------------------------------------------------------------------------
extern "C" void kernel_launch(void* const* d_in, const int* in_sizes, int n_in,
                              void* d_out, int out_size)
{
    const float* x  = (const float*)d_in[0];
    const float* Wq = (const float*)d_in[1];
    const float* bq = (const float*)d_in[2];
    const float* Wk = (const float*)d_in[3];
    const float* bk = (const float*)d_in[4];
    const float* Wv = (const float*)d_in[5];
    const float* bv = (const float*)d_in[6];
    const float* Wo = (const float*)d_in[7];
    const float* bo = (const float*)d_in[8];
    // d_in[9] = mask (causal; computed implicitly)
    float* out = (float*)d_out;

    __half *Xh, *WqT, *WkT, *WvT, *WoT, *Qh, *Kh, *Vh, *Oh, *Kpp, *Vpp;
    cudaGetSymbolAddress((void**)&Xh,  g_Xh);
    cudaGetSymbolAddress((void**)&WqT, g_WqT);
    cudaGetSymbolAddress((void**)&WkT, g_WkT);
    cudaGetSymbolAddress((void**)&WvT, g_WvT);
    cudaGetSymbolAddress((void**)&WoT, g_WoT);
    cudaGetSymbolAddress((void**)&Qh,  g_Qh);
    cudaGetSymbolAddress((void**)&Kh,  g_Kh);
    cudaGetSymbolAddress((void**)&Vh,  g_Vh);
    cudaGetSymbolAddress((void**)&Oh,  g_Oh);
    cudaGetSymbolAddress((void**)&Kpp, g_Kp);
    cudaGetSymbolAddress((void**)&Vpp, g_Vp);

    // prep: x -> fp16; W -> transposed fp16
    {
        int n4 = BS * D_MODEL / 4;
        convert_x_kernel<<<(n4 + 255) / 256, 256>>>((const float4*)x, (uint2*)Xh, n4);
        dim3 gt(32, 32, 4);
        transpose_w_kernel<<<gt, 256>>>(Wq, WqT, Wk, WkT, Wv, WvT, Wo, WoT);
    }

    size_t gemm_smem = (size_t)GSTAGES * GSTG * sizeof(uint32_t);   // 61440 B

    // fused QKV projection (fp16 HMMA, R14 config)
    {
        cudaFuncSetAttribute(gemm_qkv_f16, cudaFuncAttributeMaxDynamicSharedMemorySize,
                             (int)gemm_smem);
        dim3 g(12, BS / GBM);
        gemm_qkv_f16<<<g, 128, gemm_smem>>>(Xh, WqT, bq, Qh, WkT, bk, Kh, WvT, bv, Vh);
    }

    // repack K/V into fp16 fragment order
    {
        dim3 g(SEQ / 64, BATCH * KV_HEADS, 2);
        repack_kv_kernel<<<g, 128>>>(Kh, Vh, Kpp, Vpp);
    }

    // flash attention (fp16 HMMA, f16x2 exp)
    {
        size_t smem = (size_t)(2 * FA_STG) * sizeof(uint32_t);   // 32768 B
        cudaFuncSetAttribute(fa_f16_kernel, cudaFuncAttributeMaxDynamicSharedMemorySize,
                             (int)smem);
        dim3 g(BATCH * N_HEADS, SEQ / 64);
        fa_f16_kernel<<<g, 128, smem>>>(Qh, Kpp, Vpp, Oh);
    }

    // output projection (fp16 HMMA, fp32 out, R14 config)
    {
        cudaFuncSetAttribute(gemm_out_f16, cudaFuncAttributeMaxDynamicSharedMemorySize,
                             (int)gemm_smem);
        dim3 go(D_MODEL / GBN, BS / GBM);
        gemm_out_f16<<<go, 128, gemm_smem>>>(Oh, WoT, bo, out);
    }
}